// round 15
// baseline (speedup 1.0000x reference)
#include <cuda_runtime.h>
#include <cuda_fp16.h>
#include <math.h>
#include <stdint.h>

#define Sq 2048
#define Ed 1024
#define NHh 4
#define HDd 256
#define Bb 2
#define BHh 8
#define E3 3072

#define TM 64
#define TN 64
#define LDH 264      // half stride for Q/K/V tiles (528B: mod128=16 -> ldmatrix conflict-free)
#define PLD 72       // half stride for P tile

#define FULLMASK 0xffffffffu

// ---------------- device-global scratch ----------------
__device__ float g_ig[BHh * Sq];
__device__ float g_fg[BHh * Sq];
__device__ float g_a[BHh * Sq];
__device__ float g_pm[BHh * Sq];
__device__ float g_m[BHh * Sq];
__device__ float g_ta[BHh * (Sq / TN)];
__device__ __half g_qh[(size_t)BHh * Sq * HDd];   // [b][h][s][d]
__device__ __half g_kh[(size_t)BHh * Sq * HDd];   // [b][h][s][d]
__device__ __half g_vh[(size_t)BHh * Sq * HDd];   // [b][h][s][d]

struct alignas(8) H4 { __half2 a, b; };

// ---------------- PTX helpers ----------------
__device__ __forceinline__ void mma16(float d[4], uint32_t a0, uint32_t a1,
                                      uint32_t a2, uint32_t a3,
                                      uint32_t b0, uint32_t b1) {
    asm volatile(
        "mma.sync.aligned.m16n8k16.row.col.f32.f16.f16.f32 "
        "{%0,%1,%2,%3}, {%4,%5,%6,%7}, {%8,%9}, {%0,%1,%2,%3};\n"
        : "+f"(d[0]), "+f"(d[1]), "+f"(d[2]), "+f"(d[3])
        : "r"(a0), "r"(a1), "r"(a2), "r"(a3), "r"(b0), "r"(b1));
}

__device__ __forceinline__ void ldsm4(uint32_t& r0, uint32_t& r1, uint32_t& r2,
                                      uint32_t& r3, uint32_t addr) {
    asm volatile("ldmatrix.sync.aligned.m8n8.x4.shared.b16 {%0,%1,%2,%3}, [%4];\n"
                 : "=r"(r0), "=r"(r1), "=r"(r2), "=r"(r3) : "r"(addr));
}

__device__ __forceinline__ void ldsm4t(uint32_t& r0, uint32_t& r1, uint32_t& r2,
                                       uint32_t& r3, uint32_t addr) {
    asm volatile("ldmatrix.sync.aligned.m8n8.x4.trans.shared.b16 {%0,%1,%2,%3}, [%4];\n"
                 : "=r"(r0), "=r"(r1), "=r"(r2), "=r"(r3) : "r"(addr));
}

__device__ __forceinline__ void cpa16(uint32_t dst, const void* src) {
    asm volatile("cp.async.cg.shared.global [%0], [%1], 16;\n" :: "r"(dst), "l"(src));
}
#define CP_COMMIT() asm volatile("cp.async.commit_group;\n")
#define CP_WAIT(n)  asm volatile("cp.async.wait_group %0;\n" :: "n"(n))

// ---------------------------------------------------------------------------
// Kernel 1: gates + fp16 conversion of q,k,v into per-head layout.
// 256 blocks x 256 thr; TWO rows per warp (W L1 traffic amortized).
// No smem: W float4 loads straight from global, L1-resident (96 KB).
// ---------------------------------------------------------------------------
__global__ void __launch_bounds__(256)
gates_kernel(const float* __restrict__ q, const float* __restrict__ k,
             const float* __restrict__ v, const float* __restrict__ iw,
             const float* __restrict__ ib, const float* __restrict__ fw,
             const float* __restrict__ fb) {
    int t = threadIdx.x;
    int lane = t & 31, warp = t >> 5;
    int bs0 = (blockIdx.x * 8 + warp) * 2;     // even: both rows share b
    int b = bs0 >> 11, s0 = bs0 & (Sq - 1);

    float acc0[8], acc1[8];
    #pragma unroll
    for (int j = 0; j < 8; j++) { acc0[j] = 0.f; acc1[j] = 0.f; }

    #pragma unroll 1
    for (int sec = 0; sec < 3; sec++) {
        const float* src = (sec == 0) ? q : (sec == 1) ? k : v;
        __half* dst = (sec == 0) ? g_qh : (sec == 1) ? g_kh : g_vh;
        const float* r0 = src + (size_t)bs0 * Ed;
        const float* r1 = r0 + Ed;

        #pragma unroll
        for (int half = 0; half < 2; half++) {
            // batch 8 independent x loads (MLP=8)
            float4 x0[4], x1[4];
            #pragma unroll
            for (int cc = 0; cc < 4; cc++) {
                int fs = lane + 32 * (half * 4 + cc);
                x0[cc] = *(const float4*)(r0 + (size_t)fs * 4);
                x1[cc] = *(const float4*)(r1 + (size_t)fs * 4);
            }
            #pragma unroll
            for (int cc = 0; cc < 4; cc++) {
                int fs = lane + 32 * (half * 4 + cc);
                int rg = sec * Ed + fs * 4;      // W row of x.x
                #pragma unroll
                for (int d = 0; d < 4; d++) {
                    float e0 = (&x0[cc].x)[d];
                    float e1 = (&x1[cc].x)[d];
                    float4 wi = *(const float4*)(iw + (size_t)(rg + d) * 4);
                    float4 wf = *(const float4*)(fw + (size_t)(rg + d) * 4);
                    acc0[0] += e0 * wi.x; acc0[1] += e0 * wi.y;
                    acc0[2] += e0 * wi.z; acc0[3] += e0 * wi.w;
                    acc0[4] += e0 * wf.x; acc0[5] += e0 * wf.y;
                    acc0[6] += e0 * wf.z; acc0[7] += e0 * wf.w;
                    acc1[0] += e1 * wi.x; acc1[1] += e1 * wi.y;
                    acc1[2] += e1 * wi.z; acc1[3] += e1 * wi.w;
                    acc1[4] += e1 * wf.x; acc1[5] += e1 * wf.y;
                    acc1[6] += e1 * wf.z; acc1[7] += e1 * wf.w;
                }
                // fp16 conversion, coalesced 8B stores
                int rf = fs * 4;                 // 0..1023 within section
                int head = rf >> 8, d2 = rf & 255;
                size_t off = ((size_t)(b * NHh + head) * Sq + s0) * HDd + d2;
                H4 h0, h1;
                h0.a = __floats2half2_rn(x0[cc].x, x0[cc].y);
                h0.b = __floats2half2_rn(x0[cc].z, x0[cc].w);
                h1.a = __floats2half2_rn(x1[cc].x, x1[cc].y);
                h1.b = __floats2half2_rn(x1[cc].z, x1[cc].w);
                *(H4*)(dst + off) = h0;
                *(H4*)(dst + off + HDd) = h1;
            }
        }
    }

    #pragma unroll
    for (int off = 16; off; off >>= 1)
        #pragma unroll
        for (int j = 0; j < 8; j++) {
            acc0[j] += __shfl_xor_sync(FULLMASK, acc0[j], off);
            acc1[j] += __shfl_xor_sync(FULLMASK, acc1[j], off);
        }
    if (lane == 0) {
        #pragma unroll
        for (int h = 0; h < NHh; h++) {
            int idx = (b * NHh + h) * Sq + s0;
            g_ig[idx]     = acc0[h]     + ib[h];
            g_fg[idx]     = acc0[4 + h] + fb[h];
            g_ig[idx + 1] = acc1[h]     + ib[h];
            g_fg[idx + 1] = acc1[4 + h] + fb[h];
        }
    }
}

// ---------------------------------------------------------------------------
// Kernel 2: per-head scans + per-tile max of a[].
// ---------------------------------------------------------------------------
__global__ void scan_kernel() {
    __shared__ float sv[Sq];
    __shared__ float av[Sq];
    __shared__ float part[1024];
    int bh = blockIdx.x;
    int t = threadIdx.x;
    const float* fgp = g_fg + bh * Sq;
    const float* igp = g_ig + bh * Sq;

    for (int e = t; e < Sq; e += 1024) {
        float x = fgp[e];
        sv[e] = (x >= 0.f) ? -log1pf(expf(-x)) : (x - log1pf(expf(x)));
    }
    __syncthreads();

    float p = sv[2 * t] + sv[2 * t + 1];
    part[t] = p;
    __syncthreads();
    for (int off = 1; off < 1024; off <<= 1) {
        float x = (t >= off) ? part[t - off] : 0.f;
        __syncthreads();
        part[t] += x;
        __syncthreads();
    }
    float base = (t > 0) ? part[t - 1] : 0.f;
    float cs0 = base + sv[2 * t];
    float cs1 = cs0 + sv[2 * t + 1];
    av[2 * t]     = igp[2 * t]     - cs0;
    av[2 * t + 1] = igp[2 * t + 1] - cs1;
    __syncthreads();

    if (t < Sq / TN) {
        float mx = -3.4e38f;
        #pragma unroll 8
        for (int e = 0; e < TN; e++) mx = fmaxf(mx, av[t * TN + e]);
        g_ta[bh * (Sq / TN) + t] = mx;
    }

    part[t] = fmaxf(av[2 * t], av[2 * t + 1]);
    __syncthreads();
    for (int off = 1; off < 1024; off <<= 1) {
        float x = (t >= off) ? part[t - off] : -3.4e38f;
        __syncthreads();
        part[t] = fmaxf(part[t], x);
        __syncthreads();
    }
    float mbase = (t > 0) ? part[t - 1] : -3.4e38f;
    float pm0 = fmaxf(mbase, av[2 * t]);
    float pm1 = fmaxf(pm0, av[2 * t + 1]);

    int o = bh * Sq + 2 * t;
    g_a[o]      = av[2 * t];
    g_a[o + 1]  = av[2 * t + 1];
    g_pm[o]     = pm0;
    g_pm[o + 1] = pm1;
    g_m[o]      = cs0 + pm0;
    g_m[o + 1]  = cs1 + pm1;
}

// ---------------------------------------------------------------------------
// Kernel 3: fp16 attention, balanced pairing: 128 blocks (single wave),
// block (pr,bh) processes row tiles {31-pr, pr} -> exactly 33 col-iters each.
// P-visibility barrier is a 64-thread named barrier per (wr, wr+4) warp pair.
// ---------------------------------------------------------------------------
// smem map (halfs)
#define QS_OFF  0
#define TSZ     (TM * LDH)                 // 16896 halves per tile
#define KS_OFF  TSZ
#define VS_OFF  (KS_OFF + 2 * TSZ)
#define PS_OFF  (VS_OFF + 2 * TSZ)
#define HALF_TOT (PS_OFF + TM * PLD)       // 89088
#define FREG_BYTES (HALF_TOT * 2)          // 178176

__global__ void __launch_bounds__(256)
attn_kernel(const float* __restrict__ rms, float* __restrict__ out) {
    extern __shared__ __half smh[];
    float* fr    = (float*)((char*)smh + FREG_BYTES);
    float* npart = fr;          // 128
    float* pmr   = fr + 128;    // 64
    float* emr   = fr + 192;    // 64
    float* ejs   = fr + 256;    // 64
    float* rfac  = fr + 320;    // 64
    float* ssqp  = fr + 384;    // 128

    uint32_t smB = (uint32_t)__cvta_generic_to_shared(smh);

    int pr = blockIdx.x >> 3;             // 0..15
    int bh = blockIdx.x & 7;
    int b = bh >> 2, h = bh & 3;
    int t = threadIdx.x;
    int lane = t & 31, wid = t >> 5;
    int wr = wid & 3, wc = wid >> 2;
    int g = lane >> 2, c = lane & 3;
    const int iA = wr * 16 + g, iB = iA + 8;

    const __half* qh = g_qh + (size_t)bh * Sq * HDd;
    const __half* kh = g_kh + (size_t)bh * Sq * HDd;
    const __half* vh = g_vh + (size_t)bh * Sq * HDd;

    // per-lane ldmatrix patterns
    const int rowPat  = (lane & 7) + ((lane >> 3) & 1) * 8;   // A rows
    const int colPatA = (lane >> 4) * 8;                      // A cols
    const int rowPatB = (lane & 7) + ((lane >> 4) & 1) * 8;   // K-B rows (non-trans)
    const int colPatB = ((lane >> 3) & 1) * 8;                // K-B cols
    const int vRowL   = lane & 15;                            // V-B rows (trans)
    const int vColL   = wc * 128 + ((lane >> 4) & 1) * 8;     // V-B col base

    uint32_t aQaddr = smB + (uint32_t)(QS_OFF + (wr * 16 + rowPat) * LDH + colPatA) * 2;
    uint32_t aPaddr = smB + (uint32_t)(PS_OFF + (wr * 16 + rowPat) * PLD + colPatA) * 2;

    #pragma unroll 1
    for (int tile = 0; tile < 2; tile++) {
        int rt = tile ? pr : (Sq / TM - 1 - pr);   // heavy tile first
        int i0 = rt * TM;

        __syncthreads();   // smem safe to reinit (prev tile's readers done)

        // Q tile + K/V stage 0 (one cp.async group)
        for (int idx = t; idx < TM * 32; idx += 256) {
            int i = idx >> 5, ch = (idx & 31) << 3;
            cpa16(smB + (uint32_t)(QS_OFF + i * LDH + ch) * 2,
                  qh + (size_t)(i0 + i) * HDd + ch);
            cpa16(smB + (uint32_t)(KS_OFF + i * LDH + ch) * 2,
                  kh + (size_t)i * HDd + ch);
            cpa16(smB + (uint32_t)(VS_OFF + i * LDH + ch) * 2,
                  vh + (size_t)i * HDd + ch);
        }
        CP_COMMIT();

        if (t < 128) npart[t] = 0.f;
        if (t < TM) {
            pmr[t] = g_pm[bh * Sq + i0 + t];
            emr[t] = __expf(-g_m[bh * Sq + i0 + t]);
        }

        float accO[16][4];
        #pragma unroll
        for (int nt = 0; nt < 16; nt++)
            #pragma unroll
            for (int r = 0; r < 4; r++) accO[nt][r] = 0.f;

        #pragma unroll 1
        for (int jt = 0; jt <= rt; jt++) {
            int buf = jt & 1;
            int j0 = jt * TN;

            if (t < TM) {
                float ta = g_ta[bh * (Sq / TN) + jt];
                ejs[t]  = __expf(g_a[bh * Sq + j0 + t] - ta);
                rfac[t] = __expf(ta - pmr[t]);
            }

            CP_WAIT(0);
            __syncthreads();   // stage[buf] + ejs/rfac ready; prev readers done

            if (jt < rt) {     // prefetch next stage
                int nj0 = j0 + TN, nbuf = buf ^ 1;
                for (int idx = t; idx < TM * 32; idx += 256) {
                    int i = idx >> 5, ch = (idx & 31) << 3;
                    cpa16(smB + (uint32_t)(KS_OFF + nbuf * TSZ + i * LDH + ch) * 2,
                          kh + (size_t)(nj0 + i) * HDd + ch);
                    cpa16(smB + (uint32_t)(VS_OFF + nbuf * TSZ + i * LDH + ch) * 2,
                          vh + (size_t)(nj0 + i) * HDd + ch);
                }
                CP_COMMIT();
            }

            // ---- QK^T: rows [wr*16,+16) x cols [wc*32,+32) ----
            float acc[4][4];
            #pragma unroll
            for (int nt = 0; nt < 4; nt++)
                #pragma unroll
                for (int r = 0; r < 4; r++) acc[nt][r] = 0.f;

            uint32_t bK0 = smB + (uint32_t)(KS_OFF + buf * TSZ
                              + (wc * 32 + rowPatB) * LDH + colPatB) * 2;
            uint32_t bK1 = bK0 + 16 * LDH * 2;
            #pragma unroll
            for (int kk = 0; kk < HDd; kk += 16) {
                uint32_t a0, a1, a2, a3, b00, b01, b10, b11, b20, b21, b30, b31;
                ldsm4(a0, a1, a2, a3, aQaddr + kk * 2);
                ldsm4(b00, b01, b10, b11, bK0 + kk * 2);
                ldsm4(b20, b21, b30, b31, bK1 + kk * 2);
                mma16(acc[0], a0, a1, a2, a3, b00, b01);
                mma16(acc[1], a0, a1, a2, a3, b10, b11);
                mma16(acc[2], a0, a1, a2, a3, b20, b21);
                mma16(acc[3], a0, a1, a2, a3, b30, b31);
            }

            // ---- scale, mask, store P (half), row sums ----
            bool diag = (jt == rt);
            float rA = rfac[iA] * 0.0625f;
            float rB = rfac[iB] * 0.0625f;
            float s0 = 0.f, s1 = 0.f;
            __half* Ps = smh + PS_OFF;
            #pragma unroll
            for (int nt = 0; nt < 4; nt++) {
                int j = wc * 32 + nt * 8 + 2 * c;
                float e0 = ejs[j], e1 = ejs[j + 1];
                float p00 = acc[nt][0] * rA * e0;
                float p01 = acc[nt][1] * rA * e1;
                float p10 = acc[nt][2] * rB * e0;
                float p11 = acc[nt][3] * rB * e1;
                if (diag) {
                    if (j > iA)     p00 = 0.f;
                    if (j + 1 > iA) p01 = 0.f;
                    if (j > iB)     p10 = 0.f;
                    if (j + 1 > iB) p11 = 0.f;
                }
                *(__half2*)(Ps + iA * PLD + j) = __floats2half2_rn(p00, p01);
                *(__half2*)(Ps + iB * PLD + j) = __floats2half2_rn(p10, p11);
                s0 += p00 + p01;
                s1 += p10 + p11;
            }
            s0 += __shfl_xor_sync(FULLMASK, s0, 1);
            s0 += __shfl_xor_sync(FULLMASK, s0, 2);
            s1 += __shfl_xor_sync(FULLMASK, s1, 1);
            s1 += __shfl_xor_sync(FULLMASK, s1, 2);
            if (c == 0) {
                npart[wc * 64 + iA] += s0;
                npart[wc * 64 + iB] += s1;
            }

            // P visible to the (wr, wr+4) pair only -> named barrier, 64 thr
            asm volatile("bar.sync %0, 64;" :: "r"(wr + 1) : "memory");

            // ---- O += P @ V : rows [wr*16,+16) x d-cols [wc*128,+128) ----
            uint32_t vB = smB + (uint32_t)(VS_OFF + buf * TSZ + vRowL * LDH + vColL) * 2;
            #pragma unroll
            for (int kk = 0; kk < TN; kk += 16) {
                uint32_t a0, a1, a2, a3;
                ldsm4(a0, a1, a2, a3, aPaddr + kk * 2);
                uint32_t vRow = vB + (uint32_t)(kk * LDH) * 2;
                #pragma unroll
                for (int nb = 0; nb < 8; nb++) {
                    uint32_t b0, b1, b2, b3;
                    ldsm4t(b0, b1, b2, b3, vRow + (uint32_t)(nb * 16) * 2);
                    mma16(accO[nb * 2],     a0, a1, a2, a3, b0, b1);
                    mma16(accO[nb * 2 + 1], a0, a1, a2, a3, b2, b3);
                }
            }
        }
        __syncthreads();

        // ---- epilogue: 1/(n+eps), RMSNorm over HD=256, write out ----
        float nA = fmaxf(npart[iA] + npart[64 + iA], emr[iA]) + 1e-6f;
        float nB = fmaxf(npart[iB] + npart[64 + iB], emr[iB]) + 1e-6f;
        float invA = 1.f / nA, invB = 1.f / nB;
        float ssqA = 0.f, ssqB = 0.f;
        #pragma unroll
        for (int nt = 0; nt < 16; nt++) {
            accO[nt][0] *= invA; accO[nt][1] *= invA;
            accO[nt][2] *= invB; accO[nt][3] *= invB;
            ssqA += accO[nt][0] * accO[nt][0] + accO[nt][1] * accO[nt][1];
            ssqB += accO[nt][2] * accO[nt][2] + accO[nt][3] * accO[nt][3];
        }
        ssqA += __shfl_xor_sync(FULLMASK, ssqA, 1);
        ssqA += __shfl_xor_sync(FULLMASK, ssqA, 2);
        ssqB += __shfl_xor_sync(FULLMASK, ssqB, 1);
        ssqB += __shfl_xor_sync(FULLMASK, ssqB, 2);
        if (c == 0) {
            ssqp[wc * 64 + iA] = ssqA;
            ssqp[wc * 64 + iB] = ssqB;
        }
        __syncthreads();
        float rstdA = rsqrtf((ssqp[iA] + ssqp[64 + iA]) * (1.f / 256.f) + 1e-6f);
        float rstdB = rsqrtf((ssqp[iB] + ssqp[64 + iB]) * (1.f / 256.f) + 1e-6f);

        float* ob = out + ((size_t)(b * Sq + i0)) * Ed + h * HDd;
        #pragma unroll
        for (int nt = 0; nt < 16; nt++) {
            int col = wc * 128 + nt * 8 + 2 * c;
            float rs0 = rms[col], rs1 = rms[col + 1];
            *(float2*)(ob + (size_t)iA * Ed + col) =
                make_float2(accO[nt][0] * rstdA * (1.f + rs0),
                            accO[nt][1] * rstdA * (1.f + rs1));
            *(float2*)(ob + (size_t)iB * Ed + col) =
                make_float2(accO[nt][2] * rstdB * (1.f + rs0),
                            accO[nt][3] * rstdB * (1.f + rs1));
        }
    }
}

// ---------------------------------------------------------------------------
extern "C" void kernel_launch(void* const* d_in, const int* in_sizes, int n_in,
                              void* d_out, int out_size) {
    (void)in_sizes; (void)n_in; (void)out_size;
    const float* q   = (const float*)d_in[0];
    const float* k   = (const float*)d_in[1];
    const float* v   = (const float*)d_in[2];
    const float* iw  = (const float*)d_in[3];
    const float* ib  = (const float*)d_in[4];
    const float* fw  = (const float*)d_in[5];
    const float* fb  = (const float*)d_in[6];
    const float* rms = (const float*)d_in[7];
    float* out = (float*)d_out;

    const int attn_smem = FREG_BYTES + 512 * 4;          // 180224 B
    cudaFuncSetAttribute(attn_kernel,
                         cudaFuncAttributeMaxDynamicSharedMemorySize, attn_smem);

    gates_kernel<<<Bb * Sq / 16, 256>>>(q, k, v, iw, ib, fw, fb);
    scan_kernel<<<BHh, 1024>>>();
    attn_kernel<<<(Sq / (2 * TM)) * BHh, 256, attn_smem>>>(rms, out);
}